// round 1
// baseline (speedup 1.0000x reference)
#include <cuda_runtime.h>
#include <cuda_bf16.h>

// Problem constants (fixed by the reference):
//   N=4096 atoms, M=64 neighbors, Q=64 descriptor dim, H=64 hidden, T=4 types
#define NATOMS 4096
#define MNBR   64
#define QD     64
#define HD     64

// Per-block (per-atom) dipole partials; written fully every launch (deterministic).
__device__ float g_partials[NATOMS * 3];

// One block per atom. 192 threads.
// Phase 1 (cheap, SMEM): de_dq[64] via two 64x64 matvecs + tanh; w[m] = -r2 (min image).
// Phase 2 (the bandwidth): stream grad[i, :, :, :] (48 KiB) as float4, weighted-reduce.
__global__ __launch_bounds__(192, 8) void tnep_main(
    const float* __restrict__ desc,     // [N, Q]
    const float* __restrict__ grads,    // [N, M, 3, Q]
    const float* __restrict__ pos,      // [N, 3]
    const float* __restrict__ box,      // [3, 3]
    const float* __restrict__ W0,       // [T, Q, H]
    const float* __restrict__ b0,       // [T, H]
    const float* __restrict__ W1,       // [T, H]
    const int*   __restrict__ Z,        // [N]
    const int*   __restrict__ gidx)     // [N, M]
{
    __shared__ float W0s[QD * 65];      // padded rows: kills bank conflicts in step B
    __shared__ float desc_s[QD];
    __shared__ float gj_s[HD];
    __shared__ float de_s[QD];
    __shared__ float w_s[MNBR];
    __shared__ float sval[12];

    const int i   = blockIdx.x;
    const int tid = threadIdx.x;
    const int z   = Z[i];

    // --- load W0[z] (16 KiB) into padded SMEM, coalesced ---
    const float* W0z = W0 + (size_t)z * QD * HD;
    for (int idx = tid; idx < QD * HD; idx += 192) {
        int q = idx >> 6, j = idx & 63;
        W0s[q * 65 + j] = W0z[idx];
    }
    if (tid < QD) desc_s[tid] = desc[(size_t)i * QD + tid];

    // --- threads 64..127 compute w[m] = -r2 (overlapped with W0 load) ---
    if (tid >= 64 && tid < 128) {
        const int m = tid - 64;
        // 3x3 box inverse (redundant per thread; trivial cost)
        const float b00 = box[0], b01 = box[1], b02 = box[2];
        const float b10 = box[3], b11 = box[4], b12 = box[5];
        const float b20 = box[6], b21 = box[7], b22 = box[8];
        const float det = b00 * (b11 * b22 - b12 * b21)
                        - b01 * (b10 * b22 - b12 * b20)
                        + b02 * (b10 * b21 - b11 * b20);
        const float rd = 1.0f / det;
        const float i00 = (b11 * b22 - b12 * b21) * rd, i01 = (b02 * b21 - b01 * b22) * rd, i02 = (b01 * b12 - b02 * b11) * rd;
        const float i10 = (b12 * b20 - b10 * b22) * rd, i11 = (b00 * b22 - b02 * b20) * rd, i12 = (b02 * b10 - b00 * b12) * rd;
        const float i20 = (b10 * b21 - b11 * b20) * rd, i21 = (b01 * b20 - b00 * b21) * rd, i22 = (b00 * b11 - b01 * b10) * rd;

        const int j = gidx[(size_t)i * MNBR + m];
        const float dx = pos[j * 3 + 0] - pos[i * 3 + 0];
        const float dy = pos[j * 3 + 1] - pos[i * 3 + 1];
        const float dz = pos[j * 3 + 2] - pos[i * 3 + 2];
        // s = d @ inv_box ; s -= rint(s) ; e = s @ box   (rintf == round-half-even, matches jnp.round)
        float s0 = dx * i00 + dy * i10 + dz * i20;
        float s1 = dx * i01 + dy * i11 + dz * i21;
        float s2 = dx * i02 + dy * i12 + dz * i22;
        s0 -= rintf(s0); s1 -= rintf(s1); s2 -= rintf(s2);
        const float e0 = s0 * b00 + s1 * b10 + s2 * b20;
        const float e1 = s0 * b01 + s1 * b11 + s2 * b21;
        const float e2 = s0 * b02 + s1 * b12 + s2 * b22;
        float r2 = e0 * e0 + e1 * e1 + e2 * e2;
        if (j == i) r2 = 0.0f;            // diagonal mask from the reference
        w_s[m] = -r2;                     // fold the dipole minus sign in here
    }
    __syncthreads();

    // --- step A: g_j = (1 - tanh^2(desc . W0[:,j] + b0_j)) * W1_j ---
    if (tid < HD) {
        const int j = tid;
        float s = b0[z * HD + j];
        #pragma unroll
        for (int q = 0; q < QD; q++) s += desc_s[q] * W0s[q * 65 + j];
        const float h = tanhf(s);
        gj_s[j] = (1.0f - h * h) * W1[z * HD + j];
    }
    __syncthreads();

    // --- step B: de_dq[q] = sum_j g_j * W0[q, j] ---
    if (tid < QD) {
        const int q = tid;
        float s = 0.0f;
        #pragma unroll
        for (int j = 0; j < HD; j++) s += gj_s[j] * W0s[q * 65 + j];
        de_s[q] = s;
    }
    __syncthreads();

    // --- step D: stream this atom's gradient slab (48 KiB) ---
    // Slab = 64 m-rows * 3 channels * 64 q = 3072 float4.
    // Thread t owns fixed (c, q4) = (e4/16, e4%15) with e4 = t%48, and m-phase t/48.
    // Iteration k reads float4 index k*192 + t  ->  3072 contiguous bytes per block/iter.
    const float4* g4 = reinterpret_cast<const float4*>(grads) + (size_t)i * 3072;
    const int e4    = tid % 48;
    const int m_off = tid / 48;
    float4 acc = make_float4(0.f, 0.f, 0.f, 0.f);
    #pragma unroll
    for (int k = 0; k < 16; k++) {
        const float w = w_s[k * 4 + m_off];
        const float4 g = g4[k * 192 + tid];
        acc.x += w * g.x; acc.y += w * g.y; acc.z += w * g.z; acc.w += w * g.w;
    }
    const int q4 = e4 & 15;
    float val = acc.x * de_s[q4 * 4 + 0] + acc.y * de_s[q4 * 4 + 1]
              + acc.z * de_s[q4 * 4 + 2] + acc.w * de_s[q4 * 4 + 3];

    // reduce within aligned 16-lane groups (each group has one fixed channel c = g%3)
    #pragma unroll
    for (int off = 8; off >= 1; off >>= 1)
        val += __shfl_down_sync(0xffffffffu, val, off, 16);
    const int lane = tid & 31;
    const int warp = tid >> 5;
    if ((lane & 15) == 0) sval[warp * 2 + (lane >> 4)] = val;
    __syncthreads();
    if (tid < 3) {
        float p = 0.0f;
        #pragma unroll
        for (int g = tid; g < 12; g += 3) p += sval[g];   // group g -> channel g%3
        g_partials[i * 3 + tid] = p;
    }
}

// Deterministic final reduction: 3 blocks (one per channel), fixed-order tree.
__global__ __launch_bounds__(256) void tnep_reduce(float* __restrict__ out) {
    const int c   = blockIdx.x;
    const int tid = threadIdx.x;
    __shared__ float s[256];
    float acc = 0.0f;
    for (int idx = tid; idx < NATOMS; idx += 256) acc += g_partials[idx * 3 + c];
    s[tid] = acc;
    __syncthreads();
    #pragma unroll
    for (int off = 128; off >= 1; off >>= 1) {
        if (tid < off) s[tid] += s[tid + off];
        __syncthreads();
    }
    if (tid == 0) out[c] = s[0];
}

extern "C" void kernel_launch(void* const* d_in, const int* in_sizes, int n_in,
                              void* d_out, int out_size) {
    const float* descriptors = (const float*)d_in[0];   // [4096, 64]
    const float* gradients   = (const float*)d_in[1];   // [4096, 64, 3, 64]
    const float* positions   = (const float*)d_in[2];   // [4096, 3]
    const float* box         = (const float*)d_in[3];   // [3, 3]
    const float* W0          = (const float*)d_in[4];   // [4, 64, 64]
    const float* b0          = (const float*)d_in[5];   // [4, 64]
    const float* W1          = (const float*)d_in[6];   // [4, 64]
    const int*   Z           = (const int*)d_in[7];     // [4096]
    const int*   grad_index  = (const int*)d_in[8];     // [4096, 64]
    float* out = (float*)d_out;                         // [3]

    tnep_main<<<NATOMS, 192>>>(descriptors, gradients, positions, box,
                               W0, b0, W1, Z, grad_index);
    tnep_reduce<<<3, 256>>>(out);
}

// round 2
// speedup vs baseline: 1.0361x; 1.0361x over previous
#include <cuda_runtime.h>
#include <cuda_bf16.h>

// Problem constants (fixed by the reference):
//   N=4096 atoms, M=64 neighbors, Q=64 descriptor dim, H=64 hidden, T=4 types
#define NATOMS 4096
#define MNBR   64
#define QD     64
#define HD     64

// Per-block (per-atom) dipole partials, channel-major [3][NATOMS] for a
// coalesced final pass. Fully rewritten every launch (deterministic).
__device__ float        g_partials[3 * NATOMS];
__device__ unsigned int g_ticket = 0u;   // reset by the last block each launch

// One block per atom. 192 threads.
// Phase 1 (cheap, SMEM): de_dq[64] via two 64x64 matvecs + tanh; w[m] = -r2 (min image).
// Phase 2 (the bandwidth): stream grad[i, :, :, :] (48 KiB) as float4, weighted-reduce.
// Phase 3: last block to finish does the fixed-order final reduction (no 2nd kernel).
__global__ __launch_bounds__(192, 8) void tnep_main(
    const float* __restrict__ desc,     // [N, Q]
    const float* __restrict__ grads,    // [N, M, 3, Q]
    const float* __restrict__ pos,      // [N, 3]
    const float* __restrict__ box,      // [3, 3]
    const float* __restrict__ W0,       // [T, Q, H]
    const float* __restrict__ b0,       // [T, H]
    const float* __restrict__ W1,       // [T, H]
    const int*   __restrict__ Z,        // [N]
    const int*   __restrict__ gidx,     // [N, M]
    float*       __restrict__ out)      // [3]
{
    __shared__ float W0s[QD * 65];      // padded rows: kills bank conflicts in step B
    __shared__ float desc_s[QD];
    __shared__ float gj_s[HD];
    __shared__ float de_s[QD];
    __shared__ float w_s[MNBR];
    __shared__ float sval[12];
    __shared__ int   is_last_s;

    const int i   = blockIdx.x;
    const int tid = threadIdx.x;
    const int z   = Z[i];

    // --- load W0[z] (16 KiB) into padded SMEM, coalesced ---
    const float* W0z = W0 + (size_t)z * QD * HD;
    for (int idx = tid; idx < QD * HD; idx += 192) {
        int q = idx >> 6, j = idx & 63;
        W0s[q * 65 + j] = W0z[idx];
    }
    if (tid < QD) desc_s[tid] = desc[(size_t)i * QD + tid];

    // --- threads 64..127 compute w[m] = -r2 (overlapped with W0 load) ---
    if (tid >= 64 && tid < 128) {
        const int m = tid - 64;
        // 3x3 box inverse (redundant per thread; trivial cost)
        const float b00 = box[0], b01 = box[1], b02 = box[2];
        const float b10 = box[3], b11 = box[4], b12 = box[5];
        const float b20 = box[6], b21 = box[7], b22 = box[8];
        const float det = b00 * (b11 * b22 - b12 * b21)
                        - b01 * (b10 * b22 - b12 * b20)
                        + b02 * (b10 * b21 - b11 * b20);
        const float rd = 1.0f / det;
        const float i00 = (b11 * b22 - b12 * b21) * rd, i01 = (b02 * b21 - b01 * b22) * rd, i02 = (b01 * b12 - b02 * b11) * rd;
        const float i10 = (b12 * b20 - b10 * b22) * rd, i11 = (b00 * b22 - b02 * b20) * rd, i12 = (b02 * b10 - b00 * b12) * rd;
        const float i20 = (b10 * b21 - b11 * b20) * rd, i21 = (b01 * b20 - b00 * b21) * rd, i22 = (b00 * b11 - b01 * b10) * rd;

        const int j = gidx[(size_t)i * MNBR + m];
        const float dx = pos[j * 3 + 0] - pos[i * 3 + 0];
        const float dy = pos[j * 3 + 1] - pos[i * 3 + 1];
        const float dz = pos[j * 3 + 2] - pos[i * 3 + 2];
        // s = d @ inv_box ; s -= rint(s) ; e = s @ box   (rintf == round-half-even, matches jnp.round)
        float s0 = dx * i00 + dy * i10 + dz * i20;
        float s1 = dx * i01 + dy * i11 + dz * i21;
        float s2 = dx * i02 + dy * i12 + dz * i22;
        s0 -= rintf(s0); s1 -= rintf(s1); s2 -= rintf(s2);
        const float e0 = s0 * b00 + s1 * b10 + s2 * b20;
        const float e1 = s0 * b01 + s1 * b11 + s2 * b21;
        const float e2 = s0 * b02 + s1 * b12 + s2 * b22;
        float r2 = e0 * e0 + e1 * e1 + e2 * e2;
        if (j == i) r2 = 0.0f;            // diagonal mask from the reference
        w_s[m] = -r2;                     // fold the dipole minus sign in here
    }
    __syncthreads();

    // --- step A: g_j = (1 - tanh^2(desc . W0[:,j] + b0_j)) * W1_j ---
    if (tid < HD) {
        const int j = tid;
        float s = b0[z * HD + j];
        #pragma unroll
        for (int q = 0; q < QD; q++) s += desc_s[q] * W0s[q * 65 + j];
        const float h = tanhf(s);
        gj_s[j] = (1.0f - h * h) * W1[z * HD + j];
    }
    __syncthreads();

    // --- step B: de_dq[q] = sum_j g_j * W0[q, j] ---
    if (tid < QD) {
        const int q = tid;
        float s = 0.0f;
        #pragma unroll
        for (int j = 0; j < HD; j++) s += gj_s[j] * W0s[q * 65 + j];
        de_s[q] = s;
    }
    __syncthreads();

    // --- step D: stream this atom's gradient slab (48 KiB) ---
    // Slab = 64 m-rows * 3 channels * 64 q = 3072 float4.
    // Thread t owns fixed (c, q4) = (e4/16, e4%16) with e4 = t%48, and m-phase t/48.
    // Iteration k reads float4 index k*192 + t  ->  3072 contiguous bytes per block/iter.
    const float4* g4 = reinterpret_cast<const float4*>(grads) + (size_t)i * 3072;
    const int e4    = tid % 48;
    const int m_off = tid / 48;
    float4 acc = make_float4(0.f, 0.f, 0.f, 0.f);
    #pragma unroll
    for (int k = 0; k < 16; k++) {
        const float w = w_s[k * 4 + m_off];
        const float4 g = g4[k * 192 + tid];
        acc.x += w * g.x; acc.y += w * g.y; acc.z += w * g.z; acc.w += w * g.w;
    }
    const int q4 = e4 & 15;
    float val = acc.x * de_s[q4 * 4 + 0] + acc.y * de_s[q4 * 4 + 1]
              + acc.z * de_s[q4 * 4 + 2] + acc.w * de_s[q4 * 4 + 3];

    // reduce within aligned 16-lane groups (each group has one fixed channel c = g%3)
    #pragma unroll
    for (int off = 8; off >= 1; off >>= 1)
        val += __shfl_down_sync(0xffffffffu, val, off, 16);
    const int lane = tid & 31;
    const int warp = tid >> 5;
    if ((lane & 15) == 0) sval[warp * 2 + (lane >> 4)] = val;
    __syncthreads();

    // --- write this atom's 3 partials (thread 0 only, then fence + ticket) ---
    if (tid == 0) {
        float p0 = 0.f, p1 = 0.f, p2 = 0.f;
        #pragma unroll
        for (int g = 0; g < 12; g += 3) {   // group g holds channel g%3
            p0 += sval[g + 0];
            p1 += sval[g + 1];
            p2 += sval[g + 2];
        }
        // sval group channel mapping: group g -> channel g%3, so gather per channel
        // (g, g+1, g+2 above are groups with channels 0,1,2 respectively)
        g_partials[0 * NATOMS + i] = p0;
        g_partials[1 * NATOMS + i] = p1;
        g_partials[2 * NATOMS + i] = p2;
        __threadfence();
        unsigned int t = atomicAdd(&g_ticket, 1u);
        is_last_s = (t == (unsigned)(gridDim.x - 1)) ? 1 : 0;
    }
    __syncthreads();

    // --- phase 3: last block performs the fixed-order final reduction ---
    if (is_last_s) {
        __threadfence();
        const int c  = tid >> 6;        // 0..2 (64 threads per channel)
        const int j0 = tid & 63;
        const float* pc = g_partials + c * NATOMS;
        float a = 0.f;
        #pragma unroll 8
        for (int j = j0; j < NATOMS; j += 64) a += pc[j];
        // full-warp shuffle reduce (each warp is a uniform half of one channel)
        #pragma unroll
        for (int off = 16; off >= 1; off >>= 1)
            a += __shfl_down_sync(0xffffffffu, a, off);
        __shared__ float wsum[6];
        if ((tid & 31) == 0) wsum[tid >> 5] = a;
        __syncthreads();
        if (tid < 3) out[tid] = wsum[2 * tid] + wsum[2 * tid + 1];
        if (tid == 0) g_ticket = 0u;    // reset for the next graph replay
    }
}

extern "C" void kernel_launch(void* const* d_in, const int* in_sizes, int n_in,
                              void* d_out, int out_size) {
    const float* descriptors = (const float*)d_in[0];   // [4096, 64]
    const float* gradients   = (const float*)d_in[1];   // [4096, 64, 3, 64]
    const float* positions   = (const float*)d_in[2];   // [4096, 3]
    const float* box         = (const float*)d_in[3];   // [3, 3]
    const float* W0          = (const float*)d_in[4];   // [4, 64, 64]
    const float* b0          = (const float*)d_in[5];   // [4, 64]
    const float* W1          = (const float*)d_in[6];   // [4, 64]
    const int*   Z           = (const int*)d_in[7];     // [4096]
    const int*   grad_index  = (const int*)d_in[8];     // [4096, 64]
    float* out = (float*)d_out;                         // [3]

    tnep_main<<<NATOMS, 192>>>(descriptors, gradients, positions, box,
                               W0, b0, W1, Z, grad_index, out);
}